// round 12
// baseline (speedup 1.0000x reference)
#include <cuda_runtime.h>

#define F_DIM 128
#define NPG   100
#define KNUM  80
#define EPG   1600
#define EPG4  (EPG / 4)   // 400 int4 groups
#define TPB   256

__global__ __launch_bounds__(TPB, 8) void sagpool_fused_kernel(
    const float* __restrict__ x,
    const int*   __restrict__ ei,      // [2, E]: [0..E) = src, [E..2E) = dst
    const float* __restrict__ theta,   // [F]
    float* __restrict__ out,
    int E, int B)
{
    __shared__ float s[NPG];           // dot(x_i, theta); later self-loop term
    __shared__ float us[NPG];          // dis_i * s_i
    __shared__ float z[NPG];           // scatter accumulator -> final score
    __shared__ float dis[NPG];
    __shared__ int   degp[4][NPG];     // per-warp (warps 4..7) degree hists
    __shared__ __align__(16) int packed[EPG];   // (src-base) | (dst-base)<<7
    __shared__ float codef[NPG];       // kept ? (float)(bK+newid) : -1
    __shared__ int   inv[KNUM];
    __shared__ float scl[KNUM];
    __shared__ int   rpA[NPG];
    __shared__ int   rpB[NPG];
    __shared__ unsigned wbal[4];

    const unsigned FULL = 0xffffffffu;
    const int b     = blockIdx.x;
    const int t     = threadIdx.x;
    const int warp  = t >> 5, lane = t & 31;
    const int base  = b * NPG;
    const int ebase = b * EPG;
    const int bK    = b * KNUM;

    // ================= Phase A: warp-specialized =================
    if (warp < 4) {
        // warps 0-3: 100 dots. 8 lanes per row, 4 rows per warp per group.
        // Butterfly reduce within 8-lane groups: 3 shfl_xor instead of 5-step tree.
        const int sub  = lane & 7;        // lane within 8-group
        const int rg   = lane >> 3;       // row-group 0..3 within warp
        const float4* th4 = reinterpret_cast<const float4*>(theta);

        #pragma unroll
        for (int g = 0; g < 6; g++) {     // rows 0..95
            int row = g * 16 + warp * 4 + rg;
            const float4* xr = reinterpret_cast<const float4*>(x + (size_t)(base + row) * F_DIM);
            float4 v0 = xr[sub];
            float4 v1 = xr[sub + 8];
            float4 v2 = xr[sub + 16];
            float4 v3 = xr[sub + 24];
            float4 t0 = th4[sub];
            float4 t1 = th4[sub + 8];
            float4 t2 = th4[sub + 16];
            float4 t3 = th4[sub + 24];
            float dA = v0.x * t0.x + v0.y * t0.y + v0.z * t0.z + v0.w * t0.w;
            float dB = v1.x * t1.x + v1.y * t1.y + v1.z * t1.z + v1.w * t1.w;
            dA += v2.x * t2.x + v2.y * t2.y + v2.z * t2.z + v2.w * t2.w;
            dB += v3.x * t3.x + v3.y * t3.y + v3.z * t3.z + v3.w * t3.w;
            float d = dA + dB;
            d += __shfl_xor_sync(FULL, d, 4);
            d += __shfl_xor_sync(FULL, d, 2);
            d += __shfl_xor_sync(FULL, d, 1);
            if (sub == 0) s[row] = d;
        }
        {   // rows 96..99: one per warp, classic 32-lane dot
            int row = 96 + warp;
            float4 v  = reinterpret_cast<const float4*>(x + (size_t)(base + row) * F_DIM)[lane];
            float4 tv = th4[lane];
            float d = v.x * tv.x + v.y * tv.y + v.z * tv.z + v.w * tv.w;
            #pragma unroll
            for (int o = 16; o > 0; o >>= 1) d += __shfl_xor_sync(FULL, d, o);
            if (lane == 0) s[row] = d;
        }
    } else {
        // warps 4-7: init z + hist, load+pack edges, match-based degree histogram
        const int w  = warp - 4;
        const int tt = t - 128;            // 0..127
        for (int i = lane; i < NPG; i += 32) {
            degp[w][i] = 0;
            if (w == 0) z[i] = 0.0f;
        }
        __syncwarp();

        const int4* src4 = reinterpret_cast<const int4*>(ei + ebase);
        const int4* dst4 = reinterpret_cast<const int4*>(ei + (size_t)E + ebase);
        #pragma unroll
        for (int q0 = 0; q0 < EPG4; q0 += 128) {
            int q = q0 + tt;
            unsigned act = __ballot_sync(FULL, q < EPG4);
            if (q < EPG4) {
                int4 sv = src4[q]; int4 dv = dst4[q];
                int4 pk;
                pk.x = (sv.x - base) | ((dv.x - base) << 7);
                pk.y = (sv.y - base) | ((dv.y - base) << 7);
                pk.z = (sv.z - base) | ((dv.z - base) << 7);
                pk.w = (sv.w - base) | ((dv.w - base) << 7);
                reinterpret_cast<int4*>(packed)[q] = pk;
                int vals[4] = { pk.x & 127, pk.y & 127, pk.z & 127, pk.w & 127 };
                #pragma unroll
                for (int c = 0; c < 4; c++) {
                    unsigned grp = __match_any_sync(act, vals[c]);
                    if ((grp & ((1u << lane) - 1u)) == 0)
                        degp[w][vals[c]] += __popc(grp);
                }
            }
        }
    }
    __syncthreads();

    // ================= per-node: deg, dis, us, self term =================
    if (t < NPG) {
        int d = 1 + degp[0][t] + degp[1][t] + degp[2][t] + degp[3][t];
        float fd = (float)d;
        float r  = rsqrtf(fd);
        float sv = s[t];
        dis[t] = r;
        us[t]  = r * sv;
        s[t]   = sv / fd;
    }
    __syncthreads();

    // ================= z[dst] += dis[src]*s[src] : two static blocks =================
    {
        int4 pkA = reinterpret_cast<const int4*>(packed)[t];
        bool hasB = (t + 256) < EPG4;
        int4 pkB = hasB ? reinterpret_cast<const int4*>(packed)[t + 256] : make_int4(0,0,0,0);

        atomicAdd(&z[(pkA.x >> 7) & 127], us[pkA.x & 127]);
        atomicAdd(&z[(pkA.y >> 7) & 127], us[pkA.y & 127]);
        atomicAdd(&z[(pkA.z >> 7) & 127], us[pkA.z & 127]);
        atomicAdd(&z[(pkA.w >> 7) & 127], us[pkA.w & 127]);
        if (hasB) {
            atomicAdd(&z[(pkB.x >> 7) & 127], us[pkB.x & 127]);
            atomicAdd(&z[(pkB.y >> 7) & 127], us[pkB.y & 127]);
            atomicAdd(&z[(pkB.z >> 7) & 127], us[pkB.z & 127]);
            atomicAdd(&z[(pkB.w >> 7) & 127], us[pkB.w & 127]);
        }
    }
    __syncthreads();

    if (t < NPG) z[t] = s[t] + dis[t] * z[t];
    __syncthreads();

    // ================= rank counting, split j-halves =================
    if (t < NPG) {
        float zi = z[t]; int r = 0;
        #pragma unroll 5
        for (int j = 0; j < NPG / 2; j++) {
            float zj = z[j];
            r += (zj > zi) || (zj == zi && j < t);
        }
        rpA[t] = r;
    } else if (t >= 128 && t < 128 + NPG) {
        int i = t - 128;
        float zi = z[i]; int r = 0;
        #pragma unroll 5
        for (int j = NPG / 2; j < NPG; j++) {
            float zj = z[j];
            r += (zj > zi) || (zj == zi && j < i);
        }
        rpB[i] = r;
    }
    __syncthreads();

    // ================= kept flags (registers) + ballots =================
    int k = 0;
    if (t < 128) {
        k = (t < NPG) ? ((rpA[t] + rpB[t]) < KNUM) : 0;
        unsigned bal = __ballot_sync(FULL, k);
        if (lane == 0) wbal[warp] = bal;
    }
    __syncthreads();

    // ================= scan -> codef, inv, scl =================
    if (t < NPG) {
        int off = __popc(wbal[warp] & ((1u << lane) - 1u));
        #pragma unroll
        for (int w = 0; w < 4; w++) if (w < warp) off += __popc(wbal[w]);
        codef[t] = k ? (float)(bK + off) : -1.0f;
        if (k) {
            inv[off] = t;
            scl[off] = 1.0f / (1.0f + __expf(-z[t]));
        }
    }
    __syncthreads();

    // ================= outputs: [x_new | edge0 | edge1 | batch] =================
    const size_t EOUT0 = (size_t)B * KNUM * F_DIM;
    const size_t EOUT1 = EOUT0 + (size_t)E;
    const size_t BOUT  = EOUT0 + 2 * (size_t)E;

    // x_new: 10 rows per warp, unrolled x2 (two LDG.128 in flight)
    #pragma unroll
    for (int rr = 0; rr < 10; rr += 2) {
        int r0 = warp + 8 * rr, r1 = warp + 8 * (rr + 1);
        int i0 = inv[r0],       i1 = inv[r1];
        float sc0 = scl[r0],    sc1 = scl[r1];
        float4 v0 = reinterpret_cast<const float4*>(x + (size_t)(base + i0) * F_DIM)[lane];
        float4 v1 = reinterpret_cast<const float4*>(x + (size_t)(base + i1) * F_DIM)[lane];
        v0.x *= sc0; v0.y *= sc0; v0.z *= sc0; v0.w *= sc0;
        v1.x *= sc1; v1.y *= sc1; v1.z *= sc1; v1.w *= sc1;
        reinterpret_cast<float4*>(out + (size_t)(bK + r0) * F_DIM)[lane] = v0;
        reinterpret_cast<float4*>(out + (size_t)(bK + r1) * F_DIM)[lane] = v1;
    }

    if (t < KNUM) out[BOUT + (size_t)bK + t] = (float)b;

    // relabeled edges via codef: two static blocks
    float4* e0out = reinterpret_cast<float4*>(out + EOUT0 + ebase);
    float4* e1out = reinterpret_cast<float4*>(out + EOUT1 + ebase);
    {
        int4 pk = reinterpret_cast<const int4*>(packed)[t];
        float4 o0, o1; float cs, cd;
        cs = codef[pk.x & 127]; cd = codef[(pk.x >> 7) & 127];
        o0.x = (cd < 0.0f) ? -1.0f : cs;  o1.x = (cs < 0.0f) ? -1.0f : cd;
        cs = codef[pk.y & 127]; cd = codef[(pk.y >> 7) & 127];
        o0.y = (cd < 0.0f) ? -1.0f : cs;  o1.y = (cs < 0.0f) ? -1.0f : cd;
        cs = codef[pk.z & 127]; cd = codef[(pk.z >> 7) & 127];
        o0.z = (cd < 0.0f) ? -1.0f : cs;  o1.z = (cs < 0.0f) ? -1.0f : cd;
        cs = codef[pk.w & 127]; cd = codef[(pk.w >> 7) & 127];
        o0.w = (cd < 0.0f) ? -1.0f : cs;  o1.w = (cs < 0.0f) ? -1.0f : cd;
        e0out[t] = o0;
        e1out[t] = o1;
    }
    if (t + 256 < EPG4) {
        int q = t + 256;
        int4 pk = reinterpret_cast<const int4*>(packed)[q];
        float4 o0, o1; float cs, cd;
        cs = codef[pk.x & 127]; cd = codef[(pk.x >> 7) & 127];
        o0.x = (cd < 0.0f) ? -1.0f : cs;  o1.x = (cs < 0.0f) ? -1.0f : cd;
        cs = codef[pk.y & 127]; cd = codef[(pk.y >> 7) & 127];
        o0.y = (cd < 0.0f) ? -1.0f : cs;  o1.y = (cs < 0.0f) ? -1.0f : cd;
        cs = codef[pk.z & 127]; cd = codef[(pk.z >> 7) & 127];
        o0.z = (cd < 0.0f) ? -1.0f : cs;  o1.z = (cs < 0.0f) ? -1.0f : cd;
        cs = codef[pk.w & 127]; cd = codef[(pk.w >> 7) & 127];
        o0.w = (cd < 0.0f) ? -1.0f : cs;  o1.w = (cs < 0.0f) ? -1.0f : cd;
        e0out[q] = o0;
        e1out[q] = o1;
    }
}

extern "C" void kernel_launch(void* const* d_in, const int* in_sizes, int n_in,
                              void* d_out, int out_size)
{
    const float* x     = (const float*)d_in[0];
    const int*   ei    = (const int*)d_in[1];
    const float* theta = (const float*)d_in[3];
    float* out = (float*)d_out;

    int N = in_sizes[0] / F_DIM;   // 100000
    int E = in_sizes[1] / 2;       // 1600000
    int B = N / NPG;               // 1000

    sagpool_fused_kernel<<<B, TPB>>>(x, ei, theta, out, E, B);
}

// round 13
// speedup vs baseline: 1.4586x; 1.4586x over previous
#include <cuda_runtime.h>

#define F_DIM 128
#define NPG   100
#define KNUM  80
#define EPG   1600
#define EPG4  (EPG / 4)   // 400 int4 groups
#define TPB   256

__global__ __launch_bounds__(TPB, 8) void sagpool_fused_kernel(
    const float* __restrict__ x,
    const int*   __restrict__ ei,      // [2, E]: [0..E) = src, [E..2E) = dst
    const float* __restrict__ theta,   // [F]
    float* __restrict__ out,
    int E, int B)
{
    __shared__ float s[NPG];           // dot(x_i, theta); later self-loop term
    __shared__ float us[NPG];          // dis_i * s_i
    __shared__ float z[NPG];           // scatter accumulator -> final score
    __shared__ float dis[NPG];
    __shared__ int   degp[4][NPG];     // per-warp (warps 4..7) degree hists
    __shared__ __align__(16) int packed[EPG];   // (src-base) | (dst-base)<<7
    __shared__ float codef[NPG];       // kept ? (float)(bK+newid) : -1
    __shared__ int   inv[KNUM];
    __shared__ float scl[KNUM];
    __shared__ int   rpA[NPG];
    __shared__ int   rpB[NPG];
    __shared__ unsigned wbal[4];

    const unsigned FULL = 0xffffffffu;
    const int b     = blockIdx.x;
    const int t     = threadIdx.x;
    const int warp  = t >> 5, lane = t & 31;
    const int base  = b * NPG;
    const int ebase = b * EPG;
    const int bK    = b * KNUM;

    // ================= Phase A: warp-specialized =================
    if (warp < 4) {
        // warps 0-3: 100 dots. 8 lanes per row, 4 rows per warp per group.
        // Butterfly reduce within 8-lane groups: 3 shfl_xor instead of 5-step tree.
        const int sub  = lane & 7;        // lane within 8-group
        const int rg   = lane >> 3;       // row-group 0..3 within warp
        const float4* th4 = reinterpret_cast<const float4*>(theta);

        #pragma unroll
        for (int g = 0; g < 6; g++) {     // rows 0..95
            int row = g * 16 + warp * 4 + rg;
            const float4* xr = reinterpret_cast<const float4*>(x + (size_t)(base + row) * F_DIM);
            float4 v0 = xr[sub];
            float4 v1 = xr[sub + 8];
            float4 v2 = xr[sub + 16];
            float4 v3 = xr[sub + 24];
            float4 t0 = th4[sub];
            float4 t1 = th4[sub + 8];
            float4 t2 = th4[sub + 16];
            float4 t3 = th4[sub + 24];
            float dA = v0.x * t0.x + v0.y * t0.y + v0.z * t0.z + v0.w * t0.w;
            float dB = v1.x * t1.x + v1.y * t1.y + v1.z * t1.z + v1.w * t1.w;
            dA += v2.x * t2.x + v2.y * t2.y + v2.z * t2.z + v2.w * t2.w;
            dB += v3.x * t3.x + v3.y * t3.y + v3.z * t3.z + v3.w * t3.w;
            float d = dA + dB;
            d += __shfl_xor_sync(FULL, d, 4);
            d += __shfl_xor_sync(FULL, d, 2);
            d += __shfl_xor_sync(FULL, d, 1);
            if (sub == 0) s[row] = d;
        }
        {   // rows 96..99: one per warp, classic 32-lane dot
            int row = 96 + warp;
            float4 v  = reinterpret_cast<const float4*>(x + (size_t)(base + row) * F_DIM)[lane];
            float4 tv = th4[lane];
            float d = v.x * tv.x + v.y * tv.y + v.z * tv.z + v.w * tv.w;
            #pragma unroll
            for (int o = 16; o > 0; o >>= 1) d += __shfl_xor_sync(FULL, d, o);
            if (lane == 0) s[row] = d;
        }
    } else {
        // warps 4-7: init z + hist, load+pack edges, match-based degree histogram
        const int w  = warp - 4;
        const int tt = t - 128;            // 0..127
        for (int i = lane; i < NPG; i += 32) {
            degp[w][i] = 0;
            if (w == 0) z[i] = 0.0f;
        }
        __syncwarp();

        const int4* src4 = reinterpret_cast<const int4*>(ei + ebase);
        const int4* dst4 = reinterpret_cast<const int4*>(ei + (size_t)E + ebase);
        #pragma unroll
        for (int q0 = 0; q0 < EPG4; q0 += 128) {
            int q = q0 + tt;
            unsigned act = __ballot_sync(FULL, q < EPG4);
            if (q < EPG4) {
                int4 sv = src4[q]; int4 dv = dst4[q];
                int4 pk;
                pk.x = (sv.x - base) | ((dv.x - base) << 7);
                pk.y = (sv.y - base) | ((dv.y - base) << 7);
                pk.z = (sv.z - base) | ((dv.z - base) << 7);
                pk.w = (sv.w - base) | ((dv.w - base) << 7);
                reinterpret_cast<int4*>(packed)[q] = pk;
                int vals[4] = { pk.x & 127, pk.y & 127, pk.z & 127, pk.w & 127 };
                #pragma unroll
                for (int c = 0; c < 4; c++) {
                    unsigned grp = __match_any_sync(act, vals[c]);
                    if ((grp & ((1u << lane) - 1u)) == 0)
                        degp[w][vals[c]] += __popc(grp);
                }
            }
        }
    }
    __syncthreads();

    // ================= per-node: deg, dis, us, self term =================
    if (t < NPG) {
        int d = 1 + degp[0][t] + degp[1][t] + degp[2][t] + degp[3][t];
        float fd = (float)d;
        float r  = rsqrtf(fd);
        float sv = s[t];
        dis[t] = r;
        us[t]  = r * sv;
        s[t]   = sv / fd;
    }
    __syncthreads();

    // ================= z[dst] += dis[src]*s[src] : two static blocks =================
    {
        int4 pkA = reinterpret_cast<const int4*>(packed)[t];
        bool hasB = (t + 256) < EPG4;
        int4 pkB = hasB ? reinterpret_cast<const int4*>(packed)[t + 256] : make_int4(0,0,0,0);

        atomicAdd(&z[(pkA.x >> 7) & 127], us[pkA.x & 127]);
        atomicAdd(&z[(pkA.y >> 7) & 127], us[pkA.y & 127]);
        atomicAdd(&z[(pkA.z >> 7) & 127], us[pkA.z & 127]);
        atomicAdd(&z[(pkA.w >> 7) & 127], us[pkA.w & 127]);
        if (hasB) {
            atomicAdd(&z[(pkB.x >> 7) & 127], us[pkB.x & 127]);
            atomicAdd(&z[(pkB.y >> 7) & 127], us[pkB.y & 127]);
            atomicAdd(&z[(pkB.z >> 7) & 127], us[pkB.z & 127]);
            atomicAdd(&z[(pkB.w >> 7) & 127], us[pkB.w & 127]);
        }
    }
    __syncthreads();

    if (t < NPG) z[t] = s[t] + dis[t] * z[t];
    __syncthreads();

    // ================= rank counting, split j-halves =================
    if (t < NPG) {
        float zi = z[t]; int r = 0;
        #pragma unroll 5
        for (int j = 0; j < NPG / 2; j++) {
            float zj = z[j];
            r += (zj > zi) || (zj == zi && j < t);
        }
        rpA[t] = r;
    } else if (t >= 128 && t < 128 + NPG) {
        int i = t - 128;
        float zi = z[i]; int r = 0;
        #pragma unroll 5
        for (int j = NPG / 2; j < NPG; j++) {
            float zj = z[j];
            r += (zj > zi) || (zj == zi && j < i);
        }
        rpB[i] = r;
    }
    __syncthreads();

    // ================= kept flags (registers) + ballots =================
    int k = 0;
    if (t < 128) {
        k = (t < NPG) ? ((rpA[t] + rpB[t]) < KNUM) : 0;
        unsigned bal = __ballot_sync(FULL, k);
        if (lane == 0) wbal[warp] = bal;
    }
    __syncthreads();

    // ================= scan -> codef, inv, scl =================
    if (t < NPG) {
        int off = __popc(wbal[warp] & ((1u << lane) - 1u));
        #pragma unroll
        for (int w = 0; w < 4; w++) if (w < warp) off += __popc(wbal[w]);
        codef[t] = k ? (float)(bK + off) : -1.0f;
        if (k) {
            inv[off] = t;
            scl[off] = 1.0f / (1.0f + __expf(-z[t]));
        }
    }
    __syncthreads();

    // ================= outputs: [x_new | edge0 | edge1 | batch] =================
    const size_t EOUT0 = (size_t)B * KNUM * F_DIM;
    const size_t EOUT1 = EOUT0 + (size_t)E;
    const size_t BOUT  = EOUT0 + 2 * (size_t)E;

    // x_new: 10 rows per warp, unrolled x2 (two LDG.128 in flight)
    #pragma unroll
    for (int rr = 0; rr < 10; rr += 2) {
        int r0 = warp + 8 * rr, r1 = warp + 8 * (rr + 1);
        int i0 = inv[r0],       i1 = inv[r1];
        float sc0 = scl[r0],    sc1 = scl[r1];
        float4 v0 = reinterpret_cast<const float4*>(x + (size_t)(base + i0) * F_DIM)[lane];
        float4 v1 = reinterpret_cast<const float4*>(x + (size_t)(base + i1) * F_DIM)[lane];
        v0.x *= sc0; v0.y *= sc0; v0.z *= sc0; v0.w *= sc0;
        v1.x *= sc1; v1.y *= sc1; v1.z *= sc1; v1.w *= sc1;
        reinterpret_cast<float4*>(out + (size_t)(bK + r0) * F_DIM)[lane] = v0;
        reinterpret_cast<float4*>(out + (size_t)(bK + r1) * F_DIM)[lane] = v1;
    }

    if (t < KNUM) out[BOUT + (size_t)bK + t] = (float)b;

    // relabeled edges via codef: two static blocks
    float4* e0out = reinterpret_cast<float4*>(out + EOUT0 + ebase);
    float4* e1out = reinterpret_cast<float4*>(out + EOUT1 + ebase);
    {
        int4 pk = reinterpret_cast<const int4*>(packed)[t];
        float4 o0, o1; float cs, cd;
        cs = codef[pk.x & 127]; cd = codef[(pk.x >> 7) & 127];
        o0.x = (cd < 0.0f) ? -1.0f : cs;  o1.x = (cs < 0.0f) ? -1.0f : cd;
        cs = codef[pk.y & 127]; cd = codef[(pk.y >> 7) & 127];
        o0.y = (cd < 0.0f) ? -1.0f : cs;  o1.y = (cs < 0.0f) ? -1.0f : cd;
        cs = codef[pk.z & 127]; cd = codef[(pk.z >> 7) & 127];
        o0.z = (cd < 0.0f) ? -1.0f : cs;  o1.z = (cs < 0.0f) ? -1.0f : cd;
        cs = codef[pk.w & 127]; cd = codef[(pk.w >> 7) & 127];
        o0.w = (cd < 0.0f) ? -1.0f : cs;  o1.w = (cs < 0.0f) ? -1.0f : cd;
        e0out[t] = o0;
        e1out[t] = o1;
    }
    if (t + 256 < EPG4) {
        int q = t + 256;
        int4 pk = reinterpret_cast<const int4*>(packed)[q];
        float4 o0, o1; float cs, cd;
        cs = codef[pk.x & 127]; cd = codef[(pk.x >> 7) & 127];
        o0.x = (cd < 0.0f) ? -1.0f : cs;  o1.x = (cs < 0.0f) ? -1.0f : cd;
        cs = codef[pk.y & 127]; cd = codef[(pk.y >> 7) & 127];
        o0.y = (cd < 0.0f) ? -1.0f : cs;  o1.y = (cs < 0.0f) ? -1.0f : cd;
        cs = codef[pk.z & 127]; cd = codef[(pk.z >> 7) & 127];
        o0.z = (cd < 0.0f) ? -1.0f : cs;  o1.z = (cs < 0.0f) ? -1.0f : cd;
        cs = codef[pk.w & 127]; cd = codef[(pk.w >> 7) & 127];
        o0.w = (cd < 0.0f) ? -1.0f : cs;  o1.w = (cs < 0.0f) ? -1.0f : cd;
        e0out[q] = o0;
        e1out[q] = o1;
    }
}

extern "C" void kernel_launch(void* const* d_in, const int* in_sizes, int n_in,
                              void* d_out, int out_size)
{
    const float* x     = (const float*)d_in[0];
    const int*   ei    = (const int*)d_in[1];
    const float* theta = (const float*)d_in[3];
    float* out = (float*)d_out;

    int N = in_sizes[0] / F_DIM;   // 100000
    int E = in_sizes[1] / 2;       // 1600000
    int B = N / NPG;               // 1000

    sagpool_fused_kernel<<<B, TPB>>>(x, ei, theta, out, E, B);
}